// round 5
// baseline (speedup 1.0000x reference)
#include <cuda_runtime.h>
#include <math.h>

#define BB 64
#define SS 1024
#define DD 512
#define NROWS (BB*SS)

#define NCH 16
#define SCHUNK (SS/NCH)

#define TPB 256
#define WPB (TPB/32)
#define RPW 8            // rows per warp

#define EPS_F 1e-5f
#define MAXT 45.054565f  // asinh(sqrt(fp32_max))
#define FULL 0xffffffffu

__device__ __align__(16) float g_part[BB*NCH*DD];
__device__ __align__(16) float g_c1[BB*DD];
__device__ __align__(16) float g_mean[DD];

// ---------------------------------------------------------------------------
__device__ __forceinline__ float warp_sum(float v) {
    #pragma unroll
    for (int o = 16; o > 0; o >>= 1) v += __shfl_xor_sync(FULL, v, o);
    return v;
}

__device__ __forceinline__ float red512(float v) {
    __shared__ float sh[16];
    int w = threadIdx.x >> 5, l = threadIdx.x & 31;
    v = warp_sum(v);
    if (l == 0) sh[w] = v;
    __syncthreads();
    float r = 0.f;
    #pragma unroll
    for (int i = 0; i < 16; i++) r += sh[i];
    return r;
}

// K1a: per-(b,chunk) column partial sums over S, float4-vectorized, deep MLP
__global__ void __launch_bounds__(128) k_partial(const float* __restrict__ x) {
    int bc = blockIdx.x;            // b*NCH + c
    int t  = threadIdx.x;           // 0..127 -> float4 column t
    const float4* p = (const float4*)(x + (size_t)((bc / NCH) * SS + (bc % NCH) * SCHUNK) * DD) + t;
    float4 acc[8];
    #pragma unroll
    for (int j = 0; j < 8; j++) acc[j] = make_float4(0.f, 0.f, 0.f, 0.f);
    #pragma unroll 2
    for (int s = 0; s < SCHUNK; s += 8) {
        float4 v[8];
        #pragma unroll
        for (int j = 0; j < 8; j++) v[j] = p[(size_t)(s + j) * 128];
        #pragma unroll
        for (int j = 0; j < 8; j++) {
            acc[j].x += v[j].x; acc[j].y += v[j].y;
            acc[j].z += v[j].z; acc[j].w += v[j].w;
        }
    }
    float4 r;
    r.x = ((acc[0].x + acc[1].x) + (acc[2].x + acc[3].x)) + ((acc[4].x + acc[5].x) + (acc[6].x + acc[7].x));
    r.y = ((acc[0].y + acc[1].y) + (acc[2].y + acc[3].y)) + ((acc[4].y + acc[5].y) + (acc[6].y + acc[7].y));
    r.z = ((acc[0].z + acc[1].z) + (acc[2].z + acc[3].z)) + ((acc[4].z + acc[5].z) + (acc[6].z + acc[7].z));
    r.w = ((acc[0].w + acc[1].w) + (acc[2].w + acc[3].w)) + ((acc[4].w + acc[5].w) + (acc[6].w + acc[7].w));
    ((float4*)(g_part + (size_t)bc * DD))[t] = r;
}

// K1b: per-b centroid normalization
__global__ void k_c1() {
    int b = blockIdx.x, d = threadIdx.x;
    float a = 0.f;
    #pragma unroll
    for (int c = 0; c < NCH; c++) a += g_part[(size_t)(b * NCH + c) * DD + d];
    a *= (1.f / SS);
    float t = (d == 0) ? -a * a : a * a;
    float lin = red512(t);
    float denom = sqrtf(fmaxf(-lin, 1e-8f));
    g_c1[(size_t)b * DD + d] = a / denom;
}

// K1c: centroid over B
__global__ void k_mean() {
    int d = threadIdx.x;
    float a = 0.f;
    #pragma unroll 8
    for (int b = 0; b < BB; b++) a += g_c1[(size_t)b * DD + d];
    a *= (1.f / BB);
    float t = (d == 0) ? -a * a : a * a;
    float lin = red512(t);
    float denom = sqrtf(fmaxf(-lin, 1e-8f));
    g_mean[d] = a / denom;
}

// ---------------------------------------------------------------------------
// K2: warp-per-row, smem mean/beta, row prefetch, high occupancy
__global__ void __launch_bounds__(TPB, 4) k_main(const float* __restrict__ x,
                                                 const float* __restrict__ beta,
                                                 const float* __restrict__ gamma,
                                                 float* __restrict__ out) {
    __shared__ __align__(16) float sm_m[DD];
    __shared__ __align__(16) float sm_b[DD];

    const int ln = threadIdx.x & 31;
    const int wp = threadIdx.x >> 5;

    // cooperative load of mean/beta into smem
    {
        int t = threadIdx.x;               // 0..255, two floats each
        float2 m2 = *(const float2*)(g_mean + t * 2);
        float2 b2 = *(const float2*)(beta   + t * 2);
        *(float2*)(sm_m + t * 2) = m2;
        *(float2*)(sm_b + t * 2) = b2;
    }
    const float g = gamma[0];
    __syncthreads();

    // prologue constants (per-warp, via smem + butterfly)
    float Mss = 0.f, Bme = 0.f, Bsq = 0.f;
    #pragma unroll
    for (int k = 0; k < 4; k++) {
        float4 m4 = *(const float4*)(sm_m + k * 128 + ln * 4);
        float4 b4 = *(const float4*)(sm_b + k * 128 + ln * 4);
        Mss = fmaf(m4.x, m4.x, fmaf(m4.y, m4.y, fmaf(m4.z, m4.z, fmaf(m4.w, m4.w, Mss))));
        Bme = fmaf(b4.x, m4.x, fmaf(b4.y, m4.y, fmaf(b4.z, m4.z, fmaf(b4.w, m4.w, Bme))));
        Bsq = fmaf(b4.x, b4.x, fmaf(b4.y, b4.y, fmaf(b4.z, b4.z, fmaf(b4.w, b4.w, Bsq))));
    }
    #pragma unroll
    for (int o = 16; o > 0; o >>= 1) {
        Mss += __shfl_xor_sync(FULL, Mss, o);
        Bme += __shfl_xor_sync(FULL, Bme, o);
        Bsq += __shfl_xor_sync(FULL, Bsq, o);
    }

    const float m0  = sm_m[0];
    const float b0  = sm_b[0];
    const float BmL = Bme - 2.f * b0 * m0;                       // <beta,mean>_L
    const float Bc  = (Bsq - b0 * b0) - (1.f + b0) * (1.f + b0); // <yo,yo>_L
    const float om0 = 1.f / (1.f + m0);
    const float ob0 = 1.f / (1.f + b0);
    const bool  lead = (ln == 0);

    const size_t row0 = ((size_t)blockIdx.x * WPB + wp) * RPW;

    // prefetch row 0
    float xs[16];
    {
        const float4* px = (const float4*)(x + row0 * DD);
        #pragma unroll
        for (int k = 0; k < 4; k++) {
            float4 v = px[k * 32 + ln];
            xs[k*4+0] = v.x; xs[k*4+1] = v.y; xs[k*4+2] = v.z; xs[k*4+3] = v.w;
        }
    }

    for (int i = 0; i < RPW; i++) {
        const size_t r = row0 + i;

        // issue next row's loads before the serial math of this row
        float xn[16];
        if (i + 1 < RPW) {
            const float4* pn = (const float4*)(x + (r + 1) * DD);
            #pragma unroll
            for (int k = 0; k < 4; k++) {
                float4 v = pn[k * 32 + ln];
                xn[k*4+0] = v.x; xn[k*4+1] = v.y; xn[k*4+2] = v.z; xn[k*4+3] = v.w;
            }
        }

        // fused 4-way row sums (all Euclidean), ms/bs from smem
        float sum = 0.f, ss = 0.f, exm = 0.f, exb = 0.f;
        #pragma unroll
        for (int k = 0; k < 4; k++) {
            float4 m4 = *(const float4*)(sm_m + k * 128 + ln * 4);
            float4 b4 = *(const float4*)(sm_b + k * 128 + ln * 4);
            const float* xp = xs + k * 4;
            sum += (xp[0] + xp[1]) + (xp[2] + xp[3]);
            ss  = fmaf(xp[0], xp[0], fmaf(xp[1], xp[1], fmaf(xp[2], xp[2], fmaf(xp[3], xp[3], ss))));
            exm = fmaf(xp[0], m4.x, fmaf(xp[1], m4.y, fmaf(xp[2], m4.z, fmaf(xp[3], m4.w, exm))));
            exb = fmaf(xp[0], b4.x, fmaf(xp[1], b4.y, fmaf(xp[2], b4.z, fmaf(xp[3], b4.w, exb))));
        }
        #pragma unroll
        for (int o = 16; o > 0; o >>= 1) {
            sum += __shfl_xor_sync(FULL, sum, o);
            ss  += __shfl_xor_sync(FULL, ss,  o);
            exm += __shfl_xor_sync(FULL, exm, o);
            exb += __shfl_xor_sync(FULL, exb, o);
        }
        const float x0 = __shfl_sync(FULL, xs[0], 0);

        const float lin  = exm - 2.f * x0 * m0;   // <mean,x>_L
        const float linb = exb - 2.f * x0 * b0;   // <beta,x>_L

        const float alpha = fmaxf(-lin, 1.f + 1e-7f);
        const float dnm   = sqrtf(alpha * alpha - 1.f);
        const float coef  = acoshf(alpha) / dnm;

        const float var  = (ss - sum * sum * (1.f / DD)) * (1.f / (DD - 1));
        const float sfac = g * rsqrtf(var) + EPS_F;

        const float v0 = coef * (x0 - alpha * m0);
        const float tf = -v0 * om0;
        const float A  = coef;
        const float C  = tf - coef * alpha;

        const float N  = sfac * sfac * (A*A*ss + C*C*Mss + tf*tf
                        + 2.f*A*C*exm + 2.f*A*tf*x0 + 2.f*C*tf*m0);
        const float w0 = sfac * (A * x0 + C * m0 + tf);
        const float L  = sfac * (A * linb + C * BmL - tf * b0);

        const float scale = fminf(1.f, MAXT * rsqrtf(fmaxf(N, 1e-8f)));
        const float f = scale * L * ob0;

        float n2 = scale*scale*(N - 2.f*w0*w0) + 2.f*scale*f*(L - w0) + f*f*Bc;
        n2 = fmaxf(n2, 1e-8f);
        const float n   = sqrtf(n2);
        const float chn = coshf(n);
        const float shn = sinhf(n) / n;

        const float c1 = shn * (scale * sfac * A);
        const float c2 = shn * (scale * sfac * C);
        const float c3 = chn + shn * f;
        const float c4 = shn * (scale * sfac * tf + f);

        float4* po = (float4*)(out + r * DD);
        #pragma unroll
        for (int k = 0; k < 4; k++) {
            float4 m4 = *(const float4*)(sm_m + k * 128 + ln * 4);
            float4 b4 = *(const float4*)(sm_b + k * 128 + ln * 4);
            float4 ov;
            float o0 = fmaf(c1, xs[k*4+0], fmaf(c2, m4.x, c3 * b4.x));
            float o1 = fmaf(c1, xs[k*4+1], fmaf(c2, m4.y, c3 * b4.y));
            float o2 = fmaf(c1, xs[k*4+2], fmaf(c2, m4.z, c3 * b4.z));
            float o3 = fmaf(c1, xs[k*4+3], fmaf(c2, m4.w, c3 * b4.w));
            if (k == 0 && lead) o0 += c4;
            ov.x = o0; ov.y = o1; ov.z = o2; ov.w = o3;
            po[k * 32 + ln] = ov;
        }

        if (i + 1 < RPW) {
            #pragma unroll
            for (int j = 0; j < 16; j++) xs[j] = xn[j];
        }
    }
}

// ---------------------------------------------------------------------------
extern "C" void kernel_launch(void* const* d_in, const int* in_sizes, int n_in,
                              void* d_out, int out_size) {
    const float* x = nullptr;
    const float* beta = nullptr;
    const float* gamma = nullptr;
    for (int i = 0; i < n_in; i++) {
        if (in_sizes[i] == BB * SS * DD)      x = (const float*)d_in[i];
        else if (in_sizes[i] == DD)           beta = (const float*)d_in[i];
        else if (in_sizes[i] == 1)            gamma = (const float*)d_in[i];
    }
    float* out = (float*)d_out;

    k_partial<<<BB * NCH, 128>>>(x);
    k_c1<<<BB, DD>>>();
    k_mean<<<1, DD>>>();
    k_main<<<NROWS / (WPB * RPW), TPB>>>(x, beta, gamma, out);
}

// round 7
// speedup vs baseline: 1.4454x; 1.4454x over previous
#include <cuda_runtime.h>
#include <math.h>

#define BB 64
#define SS 1024
#define DD 512
#define NROWS (BB*SS)

#define NCH 16
#define SCHUNK (SS/NCH)

#define TPB 256
#define WPB (TPB/32)
#define RPW 4            // rows per warp

#define EPS_F 1e-5f
#define MAXT 45.054565f  // asinh(sqrt(fp32_max))
#define FULL 0xffffffffu

__device__ __align__(16) float g_part[BB*NCH*DD];
__device__ __align__(16) float g_c1[BB*DD];
__device__ __align__(16) float g_mean[DD];

// ---------------------------------------------------------------------------
__device__ __forceinline__ float warp_sum(float v) {
    #pragma unroll
    for (int o = 16; o > 0; o >>= 1) v += __shfl_xor_sync(FULL, v, o);
    return v;
}

__device__ __forceinline__ float red512(float v) {
    __shared__ float sh[16];
    int w = threadIdx.x >> 5, l = threadIdx.x & 31;
    v = warp_sum(v);
    if (l == 0) sh[w] = v;
    __syncthreads();
    float r = 0.f;
    #pragma unroll
    for (int i = 0; i < 16; i++) r += sh[i];
    return r;
}

// K1a: per-(b,chunk) column partial sums over S, float4-vectorized, deep MLP
__global__ void __launch_bounds__(128) k_partial(const float* __restrict__ x) {
    int bc = blockIdx.x;            // b*NCH + c
    int t  = threadIdx.x;           // 0..127 -> float4 column t
    const float4* p = (const float4*)(x + (size_t)((bc / NCH) * SS + (bc % NCH) * SCHUNK) * DD) + t;
    float4 acc[8];
    #pragma unroll
    for (int j = 0; j < 8; j++) acc[j] = make_float4(0.f, 0.f, 0.f, 0.f);
    #pragma unroll 2
    for (int s = 0; s < SCHUNK; s += 8) {
        float4 v[8];
        #pragma unroll
        for (int j = 0; j < 8; j++) v[j] = p[(size_t)(s + j) * 128];
        #pragma unroll
        for (int j = 0; j < 8; j++) {
            acc[j].x += v[j].x; acc[j].y += v[j].y;
            acc[j].z += v[j].z; acc[j].w += v[j].w;
        }
    }
    float4 r;
    r.x = ((acc[0].x + acc[1].x) + (acc[2].x + acc[3].x)) + ((acc[4].x + acc[5].x) + (acc[6].x + acc[7].x));
    r.y = ((acc[0].y + acc[1].y) + (acc[2].y + acc[3].y)) + ((acc[4].y + acc[5].y) + (acc[6].y + acc[7].y));
    r.z = ((acc[0].z + acc[1].z) + (acc[2].z + acc[3].z)) + ((acc[4].z + acc[5].z) + (acc[6].z + acc[7].z));
    r.w = ((acc[0].w + acc[1].w) + (acc[2].w + acc[3].w)) + ((acc[4].w + acc[5].w) + (acc[6].w + acc[7].w));
    ((float4*)(g_part + (size_t)bc * DD))[t] = r;
}

// K1b: per-b centroid normalization
__global__ void k_c1() {
    int b = blockIdx.x, d = threadIdx.x;
    float a = 0.f;
    #pragma unroll
    for (int c = 0; c < NCH; c++) a += g_part[(size_t)(b * NCH + c) * DD + d];
    a *= (1.f / SS);
    float t = (d == 0) ? -a * a : a * a;
    float lin = red512(t);
    float denom = sqrtf(fmaxf(-lin, 1e-8f));
    g_c1[(size_t)b * DD + d] = a / denom;
}

// K1c: centroid over B
__global__ void k_mean() {
    int d = threadIdx.x;
    float a = 0.f;
    #pragma unroll 8
    for (int b = 0; b < BB; b++) a += g_c1[(size_t)b * DD + d];
    a *= (1.f / BB);
    float t = (d == 0) ? -a * a : a * a;
    float lin = red512(t);
    float denom = sqrtf(fmaxf(-lin, 1e-8f));
    g_mean[d] = a / denom;
}

// ---------------------------------------------------------------------------
// K2: warp-per-row, smem mean/beta (no reg cap, no prefetch -> no spills)
__global__ void __launch_bounds__(TPB) k_main(const float* __restrict__ x,
                                              const float* __restrict__ beta,
                                              const float* __restrict__ gamma,
                                              float* __restrict__ out) {
    __shared__ __align__(16) float sm_m[DD];
    __shared__ __align__(16) float sm_b[DD];

    const int ln = threadIdx.x & 31;
    const int wp = threadIdx.x >> 5;

    // cooperative load of mean/beta into smem
    {
        int t = threadIdx.x;               // 0..255, two floats each
        float2 m2 = *(const float2*)(g_mean + t * 2);
        float2 b2 = *(const float2*)(beta   + t * 2);
        *(float2*)(sm_m + t * 2) = m2;
        *(float2*)(sm_b + t * 2) = b2;
    }
    const float g = gamma[0];
    __syncthreads();

    // prologue constants (per-warp, via smem + butterfly)
    float Mss = 0.f, Bme = 0.f, Bsq = 0.f;
    #pragma unroll
    for (int k = 0; k < 4; k++) {
        float4 m4 = *(const float4*)(sm_m + k * 128 + ln * 4);
        float4 b4 = *(const float4*)(sm_b + k * 128 + ln * 4);
        Mss = fmaf(m4.x, m4.x, fmaf(m4.y, m4.y, fmaf(m4.z, m4.z, fmaf(m4.w, m4.w, Mss))));
        Bme = fmaf(b4.x, m4.x, fmaf(b4.y, m4.y, fmaf(b4.z, m4.z, fmaf(b4.w, m4.w, Bme))));
        Bsq = fmaf(b4.x, b4.x, fmaf(b4.y, b4.y, fmaf(b4.z, b4.z, fmaf(b4.w, b4.w, Bsq))));
    }
    #pragma unroll
    for (int o = 16; o > 0; o >>= 1) {
        Mss += __shfl_xor_sync(FULL, Mss, o);
        Bme += __shfl_xor_sync(FULL, Bme, o);
        Bsq += __shfl_xor_sync(FULL, Bsq, o);
    }

    const float m0  = sm_m[0];
    const float b0  = sm_b[0];
    const float BmL = Bme - 2.f * b0 * m0;                       // <beta,mean>_L
    const float Bc  = (Bsq - b0 * b0) - (1.f + b0) * (1.f + b0); // <yo,yo>_L
    const float om0 = 1.f / (1.f + m0);
    const float ob0 = 1.f / (1.f + b0);
    const bool  lead = (ln == 0);

    const size_t row0 = ((size_t)blockIdx.x * WPB + wp) * RPW;

    for (int i = 0; i < RPW; i++) {
        const size_t r = row0 + i;
        const float4* px = (const float4*)(x + r * DD);

        float xs[16];
        #pragma unroll
        for (int k = 0; k < 4; k++) {
            float4 v = px[k * 32 + ln];
            xs[k*4+0] = v.x; xs[k*4+1] = v.y; xs[k*4+2] = v.z; xs[k*4+3] = v.w;
        }

        // fused 4-way row sums (all Euclidean), ms/bs from smem
        float sum = 0.f, ss = 0.f, exm = 0.f, exb = 0.f;
        #pragma unroll
        for (int k = 0; k < 4; k++) {
            float4 m4 = *(const float4*)(sm_m + k * 128 + ln * 4);
            float4 b4 = *(const float4*)(sm_b + k * 128 + ln * 4);
            const float* xp = xs + k * 4;
            sum += (xp[0] + xp[1]) + (xp[2] + xp[3]);
            ss  = fmaf(xp[0], xp[0], fmaf(xp[1], xp[1], fmaf(xp[2], xp[2], fmaf(xp[3], xp[3], ss))));
            exm = fmaf(xp[0], m4.x, fmaf(xp[1], m4.y, fmaf(xp[2], m4.z, fmaf(xp[3], m4.w, exm))));
            exb = fmaf(xp[0], b4.x, fmaf(xp[1], b4.y, fmaf(xp[2], b4.z, fmaf(xp[3], b4.w, exb))));
        }
        #pragma unroll
        for (int o = 16; o > 0; o >>= 1) {
            sum += __shfl_xor_sync(FULL, sum, o);
            ss  += __shfl_xor_sync(FULL, ss,  o);
            exm += __shfl_xor_sync(FULL, exm, o);
            exb += __shfl_xor_sync(FULL, exb, o);
        }
        const float x0 = __shfl_sync(FULL, xs[0], 0);

        const float lin  = exm - 2.f * x0 * m0;   // <mean,x>_L
        const float linb = exb - 2.f * x0 * b0;   // <beta,x>_L

        const float alpha = fmaxf(-lin, 1.f + 1e-7f);
        const float dnm   = sqrtf(alpha * alpha - 1.f);
        const float coef  = acoshf(alpha) / dnm;

        const float var  = (ss - sum * sum * (1.f / DD)) * (1.f / (DD - 1));
        const float sfac = g * rsqrtf(var) + EPS_F;

        const float v0 = coef * (x0 - alpha * m0);
        const float tf = -v0 * om0;
        const float A  = coef;
        const float C  = tf - coef * alpha;

        const float N  = sfac * sfac * (A*A*ss + C*C*Mss + tf*tf
                        + 2.f*A*C*exm + 2.f*A*tf*x0 + 2.f*C*tf*m0);
        const float w0 = sfac * (A * x0 + C * m0 + tf);
        const float L  = sfac * (A * linb + C * BmL - tf * b0);

        const float scale = fminf(1.f, MAXT * rsqrtf(fmaxf(N, 1e-8f)));
        const float f = scale * L * ob0;

        float n2 = scale*scale*(N - 2.f*w0*w0) + 2.f*scale*f*(L - w0) + f*f*Bc;
        n2 = fmaxf(n2, 1e-8f);
        const float n   = sqrtf(n2);
        const float chn = coshf(n);
        const float shn = sinhf(n) / n;

        const float c1 = shn * (scale * sfac * A);
        const float c2 = shn * (scale * sfac * C);
        const float c3 = chn + shn * f;
        const float c4 = shn * (scale * sfac * tf + f);

        float4* po = (float4*)(out + r * DD);
        #pragma unroll
        for (int k = 0; k < 4; k++) {
            float4 m4 = *(const float4*)(sm_m + k * 128 + ln * 4);
            float4 b4 = *(const float4*)(sm_b + k * 128 + ln * 4);
            float4 ov;
            float o0 = fmaf(c1, xs[k*4+0], fmaf(c2, m4.x, c3 * b4.x));
            float o1 = fmaf(c1, xs[k*4+1], fmaf(c2, m4.y, c3 * b4.y));
            float o2 = fmaf(c1, xs[k*4+2], fmaf(c2, m4.z, c3 * b4.z));
            float o3 = fmaf(c1, xs[k*4+3], fmaf(c2, m4.w, c3 * b4.w));
            if (k == 0 && lead) o0 += c4;
            ov.x = o0; ov.y = o1; ov.z = o2; ov.w = o3;
            po[k * 32 + ln] = ov;
        }
    }
}

// ---------------------------------------------------------------------------
extern "C" void kernel_launch(void* const* d_in, const int* in_sizes, int n_in,
                              void* d_out, int out_size) {
    const float* x = nullptr;
    const float* beta = nullptr;
    const float* gamma = nullptr;
    for (int i = 0; i < n_in; i++) {
        if (in_sizes[i] == BB * SS * DD)      x = (const float*)d_in[i];
        else if (in_sizes[i] == DD)           beta = (const float*)d_in[i];
        else if (in_sizes[i] == 1)            gamma = (const float*)d_in[i];
    }
    float* out = (float*)d_out;

    k_partial<<<BB * NCH, 128>>>(x);
    k_c1<<<BB, DD>>>();
    k_mean<<<1, DD>>>();
    k_main<<<NROWS / (WPB * RPW), TPB>>>(x, beta, gamma, out);
}

// round 9
// speedup vs baseline: 1.6213x; 1.1217x over previous
#include <cuda_runtime.h>
#include <math.h>
#include <stdint.h>

#define BB 64
#define SS 1024
#define DD 512
#define NROWS (BB*SS)

#define NCH 32
#define SCHUNK (SS/NCH)

#define TPB 256
#define WPB (TPB/32)
#define RPW 4            // rows per warp (processed 2 at a time)

#define EPS_F 1e-5f
#define MAXT 45.054565f  // asinh(sqrt(fp32_max))
#define FULL 0xffffffffu

__device__ __align__(16) float g_part[BB*NCH*DD];
__device__ __align__(16) float g_c1[BB*DD];
__device__ __align__(16) float g_mean[DD];

// ---------------------------------------------------------------------------
__device__ __forceinline__ float warp_sum(float v) {
    #pragma unroll
    for (int o = 16; o > 0; o >>= 1) v += __shfl_xor_sync(FULL, v, o);
    return v;
}

__device__ __forceinline__ float red512(float v) {
    __shared__ float sh[16];
    int w = threadIdx.x >> 5, l = threadIdx.x & 31;
    v = warp_sum(v);
    if (l == 0) sh[w] = v;
    __syncthreads();
    float r = 0.f;
    #pragma unroll
    for (int i = 0; i < 16; i++) r += sh[i];
    return r;
}

// non-hoistable 128-bit shared load
__device__ __forceinline__ float4 lds128v(uint32_t addr) {
    float4 v;
    asm volatile("ld.shared.v4.f32 {%0,%1,%2,%3}, [%4];"
                 : "=f"(v.x), "=f"(v.y), "=f"(v.z), "=f"(v.w) : "r"(addr));
    return v;
}

// K1a: per-(b,chunk) column partial sums over S, float4-vectorized
__global__ void __launch_bounds__(128) k_partial(const float* __restrict__ x) {
    int bc = blockIdx.x;            // b*NCH + c
    int t  = threadIdx.x;           // 0..127 -> float4 column t
    const float4* p = (const float4*)(x + (size_t)((bc / NCH) * SS + (bc % NCH) * SCHUNK) * DD) + t;
    float4 acc[8];
    #pragma unroll
    for (int j = 0; j < 8; j++) acc[j] = make_float4(0.f, 0.f, 0.f, 0.f);
    #pragma unroll
    for (int s = 0; s < SCHUNK; s += 8) {
        float4 v[8];
        #pragma unroll
        for (int j = 0; j < 8; j++) v[j] = p[(size_t)(s + j) * 128];
        #pragma unroll
        for (int j = 0; j < 8; j++) {
            acc[j].x += v[j].x; acc[j].y += v[j].y;
            acc[j].z += v[j].z; acc[j].w += v[j].w;
        }
    }
    float4 r;
    r.x = ((acc[0].x + acc[1].x) + (acc[2].x + acc[3].x)) + ((acc[4].x + acc[5].x) + (acc[6].x + acc[7].x));
    r.y = ((acc[0].y + acc[1].y) + (acc[2].y + acc[3].y)) + ((acc[4].y + acc[5].y) + (acc[6].y + acc[7].y));
    r.z = ((acc[0].z + acc[1].z) + (acc[2].z + acc[3].z)) + ((acc[4].z + acc[5].z) + (acc[6].z + acc[7].z));
    r.w = ((acc[0].w + acc[1].w) + (acc[2].w + acc[3].w)) + ((acc[4].w + acc[5].w) + (acc[6].w + acc[7].w));
    ((float4*)(g_part + (size_t)bc * DD))[t] = r;
}

// K1b: per-b centroid normalization
__global__ void k_c1() {
    int b = blockIdx.x, d = threadIdx.x;
    float a = 0.f;
    #pragma unroll
    for (int c = 0; c < NCH; c++) a += g_part[(size_t)(b * NCH + c) * DD + d];
    a *= (1.f / SS);
    float t = (d == 0) ? -a * a : a * a;
    float lin = red512(t);
    float denom = sqrtf(fmaxf(-lin, 1e-8f));
    g_c1[(size_t)b * DD + d] = a / denom;
}

// K1c: centroid over B
__global__ void k_mean() {
    int d = threadIdx.x;
    float a = 0.f;
    #pragma unroll 8
    for (int b = 0; b < BB; b++) a += g_c1[(size_t)b * DD + d];
    a *= (1.f / BB);
    float t = (d == 0) ? -a * a : a * a;
    float lin = red512(t);
    float denom = sqrtf(fmaxf(-lin, 1e-8f));
    g_mean[d] = a / denom;
}

// ---------------------------------------------------------------------------
// per-row scalar epilogue -> output coefficients (fast-math transcendentals)
__device__ __forceinline__ void row_coeffs(
    float sum, float ss, float exm, float exb, float x0,
    float g, float m0, float b0, float BmL, float Bc,
    float om0, float ob0, float Mss,
    float& c1, float& c2, float& c3, float& c4)
{
    const float lin  = exm - 2.f * x0 * m0;   // <mean,x>_L
    const float linb = exb - 2.f * x0 * b0;   // <beta,x>_L

    const float alpha = fmaxf(-lin, 1.f + 1e-7f);
    const float dnm   = sqrtf(alpha * alpha - 1.f);
    const float coef  = __fdividef(__logf(alpha + dnm), dnm);   // acosh(a)/sqrt(a^2-1)

    const float var  = (ss - sum * sum * (1.f / DD)) * (1.f / (DD - 1));
    const float sfac = g * rsqrtf(var) + EPS_F;

    const float v0 = coef * (x0 - alpha * m0);
    const float tf = -v0 * om0;
    const float A  = coef;
    const float C  = tf - coef * alpha;

    const float N  = sfac * sfac * (A*A*ss + C*C*Mss + tf*tf
                    + 2.f*A*C*exm + 2.f*A*tf*x0 + 2.f*C*tf*m0);
    const float w0 = sfac * (A * x0 + C * m0 + tf);
    const float L  = sfac * (A * linb + C * BmL - tf * b0);

    const float scale = fminf(1.f, MAXT * rsqrtf(fmaxf(N, 1e-8f)));
    const float f = scale * L * ob0;

    float n2 = scale*scale*(N - 2.f*w0*w0) + 2.f*scale*f*(L - w0) + f*f*Bc;
    n2 = fmaxf(n2, 1e-8f);
    const float n = sqrtf(n2);

    float chn, shn;
    if (n < 0.03f) {                      // series: rel err < 1e-7 here
        chn = 1.f + 0.5f * n2;
        shn = 1.f + n2 * (1.f / 6.f);
    } else {
        const float e  = __expf(n);
        const float ie = __fdividef(1.f, e);
        chn = 0.5f * (e + ie);
        shn = __fdividef(0.5f * (e - ie), n);
    }

    c1 = shn * (scale * sfac * A);
    c2 = shn * (scale * sfac * C);
    c3 = chn + shn * f;
    c4 = shn * (scale * sfac * tf + f);
}

// K2: warp-per-row, 2 rows interleaved, forced smem re-loads for mean/beta
__global__ void __launch_bounds__(TPB) k_main(const float* __restrict__ x,
                                              const float* __restrict__ beta,
                                              const float* __restrict__ gamma,
                                              float* __restrict__ out) {
    __shared__ __align__(16) float sm_m[DD];
    __shared__ __align__(16) float sm_b[DD];

    const int ln = threadIdx.x & 31;
    const int wp = threadIdx.x >> 5;

    {
        int t = threadIdx.x;
        float2 m2 = *(const float2*)(g_mean + t * 2);
        float2 b2 = *(const float2*)(beta   + t * 2);
        *(float2*)(sm_m + t * 2) = m2;
        *(float2*)(sm_b + t * 2) = b2;
    }
    const float g = gamma[0];
    __syncthreads();

    const uint32_t smb_m = (uint32_t)__cvta_generic_to_shared(sm_m) + ln * 16;
    const uint32_t smb_b = (uint32_t)__cvta_generic_to_shared(sm_b) + ln * 16;

    // prologue constants (plain loads fine; registers die before the loop)
    float Mss = 0.f, Bme = 0.f, Bsq = 0.f;
    #pragma unroll
    for (int k = 0; k < 4; k++) {
        float4 m4 = *(const float4*)(sm_m + k * 128 + ln * 4);
        float4 b4 = *(const float4*)(sm_b + k * 128 + ln * 4);
        Mss = fmaf(m4.x, m4.x, fmaf(m4.y, m4.y, fmaf(m4.z, m4.z, fmaf(m4.w, m4.w, Mss))));
        Bme = fmaf(b4.x, m4.x, fmaf(b4.y, m4.y, fmaf(b4.z, m4.z, fmaf(b4.w, m4.w, Bme))));
        Bsq = fmaf(b4.x, b4.x, fmaf(b4.y, b4.y, fmaf(b4.z, b4.z, fmaf(b4.w, b4.w, Bsq))));
    }
    #pragma unroll
    for (int o = 16; o > 0; o >>= 1) {
        Mss += __shfl_xor_sync(FULL, Mss, o);
        Bme += __shfl_xor_sync(FULL, Bme, o);
        Bsq += __shfl_xor_sync(FULL, Bsq, o);
    }

    const float m0  = sm_m[0];
    const float b0  = sm_b[0];
    const float BmL = Bme - 2.f * b0 * m0;
    const float Bc  = (Bsq - b0 * b0) - (1.f + b0) * (1.f + b0);
    const float om0 = 1.f / (1.f + m0);
    const float ob0 = 1.f / (1.f + b0);
    const bool  lead = (ln == 0);

    const size_t row0 = ((size_t)blockIdx.x * WPB + wp) * RPW;

    for (int i = 0; i < RPW; i += 2) {
        const size_t rA = row0 + i;
        const size_t rB = rA + 1;
        const float4* pa = (const float4*)(x + rA * DD);
        const float4* pb = (const float4*)(x + rB * DD);

        float xa[16], xb[16];
        #pragma unroll
        for (int k = 0; k < 4; k++) {
            float4 va = pa[k * 32 + ln];
            float4 vb = pb[k * 32 + ln];
            xa[k*4+0] = va.x; xa[k*4+1] = va.y; xa[k*4+2] = va.z; xa[k*4+3] = va.w;
            xb[k*4+0] = vb.x; xb[k*4+1] = vb.y; xb[k*4+2] = vb.z; xb[k*4+3] = vb.w;
        }

        // fused 8-way row sums (4 per row)
        float sA = 0.f, qA = 0.f, mA = 0.f, bA = 0.f;
        float sB = 0.f, qB = 0.f, mB = 0.f, bB = 0.f;
        #pragma unroll
        for (int k = 0; k < 4; k++) {
            const float4 m4 = lds128v(smb_m + k * 512);
            const float4 b4 = lds128v(smb_b + k * 512);
            const float* a = xa + k * 4;
            const float* b = xb + k * 4;
            sA += (a[0] + a[1]) + (a[2] + a[3]);
            sB += (b[0] + b[1]) + (b[2] + b[3]);
            qA = fmaf(a[0], a[0], fmaf(a[1], a[1], fmaf(a[2], a[2], fmaf(a[3], a[3], qA))));
            qB = fmaf(b[0], b[0], fmaf(b[1], b[1], fmaf(b[2], b[2], fmaf(b[3], b[3], qB))));
            mA = fmaf(a[0], m4.x, fmaf(a[1], m4.y, fmaf(a[2], m4.z, fmaf(a[3], m4.w, mA))));
            mB = fmaf(b[0], m4.x, fmaf(b[1], m4.y, fmaf(b[2], m4.z, fmaf(b[3], m4.w, mB))));
            bA = fmaf(a[0], b4.x, fmaf(a[1], b4.y, fmaf(a[2], b4.z, fmaf(a[3], b4.w, bA))));
            bB = fmaf(b[0], b4.x, fmaf(b[1], b4.y, fmaf(b[2], b4.z, fmaf(b[3], b4.w, bB))));
        }
        #pragma unroll
        for (int o = 16; o > 0; o >>= 1) {
            sA += __shfl_xor_sync(FULL, sA, o);
            sB += __shfl_xor_sync(FULL, sB, o);
            qA += __shfl_xor_sync(FULL, qA, o);
            qB += __shfl_xor_sync(FULL, qB, o);
            mA += __shfl_xor_sync(FULL, mA, o);
            mB += __shfl_xor_sync(FULL, mB, o);
            bA += __shfl_xor_sync(FULL, bA, o);
            bB += __shfl_xor_sync(FULL, bB, o);
        }
        const float x0A = __shfl_sync(FULL, xa[0], 0);
        const float x0B = __shfl_sync(FULL, xb[0], 0);

        float c1A, c2A, c3A, c4A, c1B, c2B, c3B, c4B;
        row_coeffs(sA, qA, mA, bA, x0A, g, m0, b0, BmL, Bc, om0, ob0, Mss,
                   c1A, c2A, c3A, c4A);
        row_coeffs(sB, qB, mB, bB, x0B, g, m0, b0, BmL, Bc, om0, ob0, Mss,
                   c1B, c2B, c3B, c4B);

        float4* poA = (float4*)(out + rA * DD);
        float4* poB = (float4*)(out + rB * DD);
        #pragma unroll
        for (int k = 0; k < 4; k++) {
            const float4 m4 = lds128v(smb_m + k * 512);
            const float4 b4 = lds128v(smb_b + k * 512);
            float4 oa, ob;
            oa.x = fmaf(c1A, xa[k*4+0], fmaf(c2A, m4.x, c3A * b4.x));
            oa.y = fmaf(c1A, xa[k*4+1], fmaf(c2A, m4.y, c3A * b4.y));
            oa.z = fmaf(c1A, xa[k*4+2], fmaf(c2A, m4.z, c3A * b4.z));
            oa.w = fmaf(c1A, xa[k*4+3], fmaf(c2A, m4.w, c3A * b4.w));
            ob.x = fmaf(c1B, xb[k*4+0], fmaf(c2B, m4.x, c3B * b4.x));
            ob.y = fmaf(c1B, xb[k*4+1], fmaf(c2B, m4.y, c3B * b4.y));
            ob.z = fmaf(c1B, xb[k*4+2], fmaf(c2B, m4.z, c3B * b4.z));
            ob.w = fmaf(c1B, xb[k*4+3], fmaf(c2B, m4.w, c3B * b4.w));
            if (k == 0 && lead) { oa.x += c4A; ob.x += c4B; }
            poA[k * 32 + ln] = oa;
            poB[k * 32 + ln] = ob;
        }
    }
}

// ---------------------------------------------------------------------------
extern "C" void kernel_launch(void* const* d_in, const int* in_sizes, int n_in,
                              void* d_out, int out_size) {
    const float* x = nullptr;
    const float* beta = nullptr;
    const float* gamma = nullptr;
    for (int i = 0; i < n_in; i++) {
        if (in_sizes[i] == BB * SS * DD)      x = (const float*)d_in[i];
        else if (in_sizes[i] == DD)           beta = (const float*)d_in[i];
        else if (in_sizes[i] == 1)            gamma = (const float*)d_in[i];
    }
    float* out = (float*)d_out;

    k_partial<<<BB * NCH, 128>>>(x);
    k_c1<<<BB, DD>>>();
    k_mean<<<1, DD>>>();
    k_main<<<NROWS / (WPB * RPW), TPB>>>(x, beta, gamma, out);
}